// round 13
// baseline (speedup 1.0000x reference)
#include <cuda_runtime.h>
#include <cuda_bf16.h>
#include <math.h>
#include <cstdint>

#define NN 512
#define D  32
#define M  32
#define HM 64
#define NSTEPS 5

typedef unsigned int u32;

// ---- scratch (device globals; no allocation allowed) ----
__device__ float g_h[2][NN*D];
__device__ float g_A[NN*HM];
__device__ float g_B[NN*HM];
__device__ float g_msgsum[NN*M];
__device__ u32 g_W2phi[32*64], g_W2plo[32*64];
__device__ u32 g_W3phi[32*32], g_W3plo[32*32];

__device__ __forceinline__ float sigmoidf(float x){ return 1.f/(1.f+expf(-x)); }

__device__ __forceinline__ void split2(float v0, float v1, u32& hi, u32& lo){
    __nv_bfloat162 h = __float22bfloat162_rn(make_float2(v0, v1));
    float r0 = v0 - __low2float(h), r1 = v1 - __high2float(h);
    __nv_bfloat162 l = __float22bfloat162_rn(make_float2(r0, r1));
    hi = *(u32*)&h; lo = *(u32*)&l;
}

// warp-level bf16 MMA, f32 accum (baseline PTX, sm_80+)
__device__ __forceinline__ void mma16816(float* c, const u32* a, u32 b0, u32 b1){
    asm volatile("mma.sync.aligned.m16n8k16.row.col.f32.bf16.bf16.f32 "
        "{%0,%1,%2,%3}, {%4,%5,%6,%7}, {%8,%9}, {%0,%1,%2,%3};"
        : "+f"(c[0]),"+f"(c[1]),"+f"(c[2]),"+f"(c[3])
        : "r"(a[0]),"r"(a[1]),"r"(a[2]),"r"(a[3]), "r"(b0),"r"(b1));
}

// ---- pack weights into bf16x2 hi/lo planes (constant per replay) ----
__global__ void split_kernel(const float* __restrict__ W2, const float* __restrict__ W3){
    int t = blockIdx.x*512 + threadIdx.x;
    if (t < 32*64){                       // B[k][n] = W2[n][k]
        int k2 = t>>6, n = t&63;
        u32 hi, lo; split2(W2[n*HM + 2*k2], W2[n*HM + 2*k2+1], hi, lo);
        g_W2phi[t] = hi; g_W2plo[t] = lo;
    } else if (t < 32*64 + 32*32){        // B[k][n] = W3[n][k]
        int u = t - 32*64;
        int k2 = u>>5, n = u&31;
        u32 hi, lo; split2(W3[n*HM + 2*k2], W3[n*HM + 2*k2+1], hi, lo);
        g_W3phi[u] = hi; g_W3plo[u] = lo;
    }
}

// ---- init: h0=0, msgsum=0, A/B for step 0 (h=0 => bias-only) ----
// mp_W1 is (64,67): [Wi(32) | Wj(32) | wJ | wbi | wbj]
__global__ __launch_bounds__(512) void init_kernel(const float* __restrict__ b,
        const float* __restrict__ W1, const float* __restrict__ b1){
    int t = blockIdx.x*512 + threadIdx.x;
    int i = t>>6, k = t&63;
    float bi = b[i];
    g_A[t] = b1[k] + bi*W1[k*67+65];
    g_B[t] = bi*W1[k*67+66];
    if (k < D) g_h[0][i*D+k] = 0.f;
    else       g_msgsum[i*M + (k-D)] = 0.f;
}

// ---------------------------------------------------------------------------
// Edge kernel (HMMA): block = 4 warps; tile = 8 i x 32 j via FOUR passes
// (2 i-passes x 2 j-passes) reusing staged weights. Warp per pass: 1 i x 16 j.
// ---------------------------------------------------------------------------
__global__ __launch_bounds__(128) void edge_kernel(const float* __restrict__ J,
        const float* __restrict__ W1, const float* __restrict__ b2,
        const float* __restrict__ b3){
    __shared__ u32   s_wbuf[7168];        // w2h[2304] w2l[2304] w3h[1280] w3l[1280]
    __shared__ float s_A[8][HM];
    __shared__ float s_B[32][72];         // padded: frag reads conflict-free
    __shared__ float s_red[4*16*33];      // 4 warps x 16 rows x 33 (padded)
    __shared__ float s_wJ[HM], s_b2[HM], s_b3[M];

    u32* s_w2h = s_wbuf;
    u32* s_w2l = s_wbuf + 2304;
    u32* s_w3h = s_wbuf + 4608;
    u32* s_w3l = s_wbuf + 5888;

    const int tid  = threadIdx.x;
    const int wid  = tid>>5, lane = tid&31;
    const int g    = lane>>2, t = lane&3;
    const int j0   = blockIdx.x*32;
    const int i0   = blockIdx.y*8;

    // ---- stage packed weights + A/B rows + vectors ----
    {
        const uint4* s2h = (const uint4*)g_W2phi;
        const uint4* s2l = (const uint4*)g_W2plo;
        #pragma unroll
        for (int idx = tid; idx < 512; idx += 128){
            int r = idx>>4, c4 = idx&15;
            *(uint4*)(s_w2h + r*72 + c4*4) = s2h[idx];
            *(uint4*)(s_w2l + r*72 + c4*4) = s2l[idx];
        }
        const uint4* s3h = (const uint4*)g_W3phi;
        const uint4* s3l = (const uint4*)g_W3plo;
        #pragma unroll
        for (int idx = tid; idx < 256; idx += 128){
            int r = idx>>3, c4 = idx&7;
            *(uint4*)(s_w3h + r*40 + c4*4) = s3h[idx];
            *(uint4*)(s_w3l + r*40 + c4*4) = s3l[idx];
        }
        const float4* Bg = (const float4*)(g_B + j0*HM);
        #pragma unroll
        for (int idx = tid; idx < 512; idx += 128){
            int r = idx>>4, c4 = idx&15;
            *(float4*)(&s_B[r][c4*4]) = Bg[idx];
        }
        const float4* Ag = (const float4*)(g_A + i0*HM);
        #pragma unroll
        for (int idx = tid; idx < 128; idx += 128)
            *(float4*)(((float*)s_A) + idx*4) = Ag[idx];
        if (tid < HM){ s_wJ[tid] = W1[tid*67+64]; s_b2[tid] = b2[tid]; }
        if (tid < M)  s_b3[tid] = b3[tid];
    }

    // prefetch all 8 J values (2 per pass) before the barrier
    float Jp[4][2];
    #pragma unroll
    for (int ip = 0; ip < 2; ip++){
        const int i = i0 + ip*4 + wid;
        #pragma unroll
        for (int jp = 0; jp < 2; jp++){
            Jp[ip*2+jp][0] = J[i*NN + j0 + jp*16 + g];
            Jp[ip*2+jp][1] = J[i*NN + j0 + jp*16 + g + 8];
        }
    }
    __syncthreads();

    #pragma unroll
    for (int pass = 0; pass < 4; pass++){
        const int ip = pass>>1, jb = (pass&1)*16;
        const int ia = ip*4 + wid;               // row in s_A
        const float Jg = Jp[pass][0], Jg8 = Jp[pass][1];

        // ---- m1 A-fragments (4 k-steps x 4 regs, hi/lo) ----
        u32 ahi[4][4], alo[4][4];
        #pragma unroll
        for (int kk = 0; kk < 4; kk++){
            #pragma unroll
            for (int h = 0; h < 2; h++){
                int k = kk*16 + h*8 + t*2;
                float A0 = s_A[ia][k],  A1 = s_A[ia][k+1];
                float w0 = s_wJ[k],     w1 = s_wJ[k+1];
                float t0 = A0 + Jg *w0, t1 = A1 + Jg *w1;
                float u0 = A0 + Jg8*w0, u1 = A1 + Jg8*w1;
                float vg0 = fmaxf(t0 + s_B[jb+g  ][k], 0.f), vg1 = fmaxf(t1 + s_B[jb+g  ][k+1], 0.f);
                float v80 = fmaxf(u0 + s_B[jb+g+8][k], 0.f), v81 = fmaxf(u1 + s_B[jb+g+8][k+1], 0.f);
                split2(vg0, vg1, ahi[kk][2*h  ], alo[kk][2*h  ]);
                split2(v80, v81, ahi[kk][2*h+1], alo[kk][2*h+1]);
            }
        }

        // ---- GEMM1: C1[16x64] = m1 @ W2^T (3-term bf16) ----
        float C1[8][4];
        #pragma unroll
        for (int nt = 0; nt < 8; nt++){ C1[nt][0]=C1[nt][1]=C1[nt][2]=C1[nt][3]=0.f; }
        #pragma unroll
        for (int nt = 0; nt < 8; nt++){
            #pragma unroll
            for (int kk = 0; kk < 4; kk++){
                const u32* bh = s_w2h + (kk*8+t)*72 + nt*8 + g;
                const u32* bl = s_w2l + (kk*8+t)*72 + nt*8 + g;
                u32 bh0 = bh[0], bh1 = bh[4*72];
                u32 bl0 = bl[0], bl1 = bl[4*72];
                mma16816(C1[nt], ahi[kk], bh0, bh1);
                mma16816(C1[nt], alo[kk], bh0, bh1);
                mma16816(C1[nt], ahi[kk], bl0, bl1);
            }
        }

        // ---- m2 = relu(C1+b2): C-frag layout == A-frag layout (regs only) ----
        u32 mhi[4][4], mlo[4][4];
        #pragma unroll
        for (int kk = 0; kk < 4; kk++){
            #pragma unroll
            for (int p = 0; p < 2; p++){
                int nt = 2*kk + p;
                float bb0 = s_b2[nt*8 + t*2], bb1 = s_b2[nt*8 + t*2 + 1];
                float v0 = fmaxf(C1[nt][0]+bb0, 0.f), v1 = fmaxf(C1[nt][1]+bb1, 0.f);
                float v2 = fmaxf(C1[nt][2]+bb0, 0.f), v3 = fmaxf(C1[nt][3]+bb1, 0.f);
                split2(v0, v1, mhi[kk][2*p  ], mlo[kk][2*p  ]);
                split2(v2, v3, mhi[kk][2*p+1], mlo[kk][2*p+1]);
            }
        }

        // ---- GEMM2: C2[16x32] = m2 @ W3^T (3-term bf16) ----
        float C2[4][4];
        #pragma unroll
        for (int nt = 0; nt < 4; nt++){ C2[nt][0]=C2[nt][1]=C2[nt][2]=C2[nt][3]=0.f; }
        #pragma unroll
        for (int nt = 0; nt < 4; nt++){
            #pragma unroll
            for (int kk = 0; kk < 4; kk++){
                const u32* bh = s_w3h + (kk*8+t)*40 + nt*8 + g;
                const u32* bl = s_w3l + (kk*8+t)*40 + nt*8 + g;
                u32 bh0 = bh[0], bh1 = bh[4*40];
                u32 bl0 = bl[0], bl1 = bl[4*40];
                mma16816(C2[nt], mhi[kk], bh0, bh1);
                mma16816(C2[nt], mlo[kk], bh0, bh1);
                mma16816(C2[nt], mhi[kk], bl0, bl1);
            }
        }

        // ---- msg = relu(C2+b3); reduce over 4 warps (i's); atomics per j ----
        #pragma unroll
        for (int nt = 0; nt < 4; nt++){
            int c = nt*8 + t*2;
            float bb0 = s_b3[c], bb1 = s_b3[c+1];
            s_red[wid*528 + g*33     + c    ] = fmaxf(C2[nt][0]+bb0, 0.f);
            s_red[wid*528 + g*33     + c + 1] = fmaxf(C2[nt][1]+bb1, 0.f);
            s_red[wid*528 + (g+8)*33 + c    ] = fmaxf(C2[nt][2]+bb0, 0.f);
            s_red[wid*528 + (g+8)*33 + c + 1] = fmaxf(C2[nt][3]+bb1, 0.f);
        }
        __syncthreads();
        #pragma unroll
        for (int v = tid; v < 512; v += 128){
            int r = v>>5, c = v&31;
            float s = s_red[r*33+c] + s_red[528+r*33+c] + s_red[1056+r*33+c] + s_red[1584+r*33+c];
            atomicAdd(&g_msgsum[(j0+jb+r)*M + c], s);
        }
        __syncthreads();   // protect s_red before next pass rewrites it
    }
}

// ---------------------------------------------------------------------------
// Update: 1 node per block, 160 threads, NO smem weight staging.
// Threads 0..95: gate rows (Wih/Whh rows preloaded as batched float4 LDGs).
// Threads 96..159: next-step A/B prep (direct __ldg W1 row reads).
// 512 small blocks => ~3 blocks/SM concurrently, latency fully overlapped.
// ---------------------------------------------------------------------------
__global__ __launch_bounds__(160) void update_kernel(
        const float* __restrict__ Wih, const float* __restrict__ Whh,
        const float* __restrict__ bih, const float* __restrict__ bhh,
        const float* __restrict__ b,   const float* __restrict__ W1,
        const float* __restrict__ b1,  int cur, int nxt){
    __shared__ float xs[D+M], gi[3*D], gh[3*D], hn[D];
    const int n = blockIdx.x, tid = threadIdx.x;

    if (tid < D+M)
        xs[tid] = (tid < D) ? g_h[cur][n*D + tid] : g_msgsum[n*M + (tid - D)];

    float4 wa[16], wb[8];
    float bi_g = 0.f, bh_g = 0.f;
    if (tid < 3*D){
        const float4* Wr = (const float4*)(Wih + tid*(D+M));
        #pragma unroll
        for (int q = 0; q < 16; q++) wa[q] = __ldg(Wr + q);
        const float4* Hr = (const float4*)(Whh + tid*D);
        #pragma unroll
        for (int q = 0; q < 8; q++) wb[q] = __ldg(Hr + q);
        bi_g = __ldg(bih + tid); bh_g = __ldg(bhh + tid);
    }
    __syncthreads();

    if (tid < 3*D){
        float a0 = bi_g, a1 = 0.f, a2 = 0.f, a3 = 0.f;
        #pragma unroll
        for (int q = 0; q < 16; q++){
            a0 = fmaf(wa[q].x, xs[q*4+0], a0); a1 = fmaf(wa[q].y, xs[q*4+1], a1);
            a2 = fmaf(wa[q].z, xs[q*4+2], a2); a3 = fmaf(wa[q].w, xs[q*4+3], a3);
        }
        gi[tid] = (a0+a1)+(a2+a3);
        float h0 = bh_g, h1 = 0.f, h2 = 0.f, h3 = 0.f;
        #pragma unroll
        for (int q = 0; q < 8; q++){
            h0 = fmaf(wb[q].x, xs[q*4+0], h0); h1 = fmaf(wb[q].y, xs[q*4+1], h1);
            h2 = fmaf(wb[q].z, xs[q*4+2], h2); h3 = fmaf(wb[q].w, xs[q*4+3], h3);
        }
        gh[tid] = (h0+h1)+(h2+h3);
    }
    __syncthreads();

    if (tid < D){
        float rr = sigmoidf(gi[tid]     + gh[tid]);
        float zz = sigmoidf(gi[D+tid]   + gh[D+tid]);
        float ng = tanhf   (gi[2*D+tid] + rr*gh[2*D+tid]);
        float hv = (1.f-zz)*ng + zz*xs[tid];
        hn[tid] = hv;
        g_h[nxt][n*D+tid] = hv;
        g_msgsum[n*M+tid] = 0.f;              // re-zero for next step
    }
    __syncthreads();

    if (tid >= 96){                            // next-step A/B from h_new
        const int k = tid - 96;                // 0..63
        const float* row = W1 + k*67;
        const float bi = __ldg(b + n);
        float a  = __ldg(b1 + k) + bi*__ldg(row+65);
        float bb = bi*__ldg(row+66);
        float ax = 0.f, bx = 0.f;
        #pragma unroll
        for (int d0 = 0; d0 < D; d0 += 2){
            float h0 = hn[d0], h1 = hn[d0+1];
            a  = fmaf(h0, __ldg(row+d0),     a);   ax = fmaf(h1, __ldg(row+d0+1),   ax);
            bb = fmaf(h0, __ldg(row+D+d0),  bb);   bx = fmaf(h1, __ldg(row+D+d0+1), bx);
        }
        g_A[n*HM+k] = a + ax;
        g_B[n*HM+k] = bb + bx;
    }
}

// ---- readout ----
__global__ void readout_kernel(const float* __restrict__ rW1,const float* __restrict__ rb1,
        const float* __restrict__ rW2,const float* __restrict__ rb2,
        const float* __restrict__ rW3,const float* __restrict__ rb3,
        int cur, float* __restrict__ out){
    __shared__ float hs[D], y1[HM], y2[HM];
    const int n = blockIdx.x, t = threadIdx.x;
    if (t < D) hs[t] = g_h[cur][n*D+t];
    __syncthreads();
    float a = rb1[t];
    #pragma unroll
    for (int c = 0; c < D; c++) a = fmaf(rW1[t*D+c], hs[c], a);
    y1[t] = fmaxf(a, 0.f);
    __syncthreads();
    a = rb2[t];
    #pragma unroll
    for (int c = 0; c < HM; c++) a = fmaf(rW2[t*HM+c], y1[c], a);
    y2[t] = fmaxf(a, 0.f);
    __syncthreads();
    if (t < 2){
        a = rb3[t];
        #pragma unroll
        for (int c = 0; c < HM; c++) a = fmaf(rW3[t*HM+c], y2[c], a);
        out[n*2+t] = 1.f/(1.f+expf(-fmaxf(a, 0.f)));
    }
}

extern "C" void kernel_launch(void* const* d_in, const int* in_sizes, int n_in,
                              void* d_out, int out_size){
    const float* J  =(const float*)d_in[0];
    const float* b  =(const float*)d_in[1];
    const float* W1 =(const float*)d_in[2];
    const float* b1 =(const float*)d_in[3];
    const float* W2 =(const float*)d_in[4];
    const float* b2 =(const float*)d_in[5];
    const float* W3 =(const float*)d_in[6];
    const float* b3 =(const float*)d_in[7];
    const float* Wih=(const float*)d_in[8];
    const float* Whh=(const float*)d_in[9];
    const float* bih=(const float*)d_in[10];
    const float* bhh=(const float*)d_in[11];
    const float* rW1=(const float*)d_in[12];
    const float* rb1=(const float*)d_in[13];
    const float* rW2=(const float*)d_in[14];
    const float* rb2=(const float*)d_in[15];
    const float* rW3=(const float*)d_in[16];
    const float* rb3=(const float*)d_in[17];
    float* out = (float*)d_out;

    init_kernel<<<64,512>>>(b, W1, b1);
    split_kernel<<<6,512>>>(W2, W3);

    int cur = 0;
    for (int s = 0; s < NSTEPS; s++){
        edge_kernel<<<dim3(NN/32, NN/8),128>>>(J, W1, b2, b3);
        update_kernel<<<NN,160>>>(Wih, Whh, bih, bhh, b, W1, b1, cur, 1-cur);
        cur = 1-cur;
    }
    readout_kernel<<<NN,HM>>>(rW1, rb1, rW2, rb2, rW3, rb3, cur, out);
}

// round 16
// speedup vs baseline: 1.0436x; 1.0436x over previous
#include <cuda_runtime.h>
#include <cuda_bf16.h>
#include <math.h>
#include <cstdint>

#define NN 512
#define D  32
#define M  32
#define HM 64
#define NSTEPS 5

typedef unsigned int u32;

// ---- scratch (device globals; no allocation allowed) ----
__device__ float g_h[2][NN*D];
__device__ float g_A[NN*HM];
__device__ float g_B[NN*HM];
__device__ float g_msgsum[NN*M];
__device__ u32 g_W2phi[32*64], g_W2plo[32*64];
__device__ u32 g_W3phi[32*32], g_W3plo[32*32];

__device__ __forceinline__ float sigmoidf(float x){ return 1.f/(1.f+expf(-x)); }

__device__ __forceinline__ void split2(float v0, float v1, u32& hi, u32& lo){
    __nv_bfloat162 h = __float22bfloat162_rn(make_float2(v0, v1));
    float r0 = v0 - __low2float(h), r1 = v1 - __high2float(h);
    __nv_bfloat162 l = __float22bfloat162_rn(make_float2(r0, r1));
    hi = *(u32*)&h; lo = *(u32*)&l;
}

// warp-level bf16 MMA, f32 accum (baseline PTX, sm_80+)
__device__ __forceinline__ void mma16816(float* c, const u32* a, u32 b0, u32 b1){
    asm volatile("mma.sync.aligned.m16n8k16.row.col.f32.bf16.bf16.f32 "
        "{%0,%1,%2,%3}, {%4,%5,%6,%7}, {%8,%9}, {%0,%1,%2,%3};"
        : "+f"(c[0]),"+f"(c[1]),"+f"(c[2]),"+f"(c[3])
        : "r"(a[0]),"r"(a[1]),"r"(a[2]),"r"(a[3]), "r"(b0),"r"(b1));
}

// ---- pack weights into bf16x2 hi/lo planes (constant per replay) ----
__global__ void split_kernel(const float* __restrict__ W2, const float* __restrict__ W3){
    int t = blockIdx.x*512 + threadIdx.x;
    if (t < 32*64){                       // B[k][n] = W2[n][k]
        int k2 = t>>6, n = t&63;
        u32 hi, lo; split2(W2[n*HM + 2*k2], W2[n*HM + 2*k2+1], hi, lo);
        g_W2phi[t] = hi; g_W2plo[t] = lo;
    } else if (t < 32*64 + 32*32){        // B[k][n] = W3[n][k]
        int u = t - 32*64;
        int k2 = u>>5, n = u&31;
        u32 hi, lo; split2(W3[n*HM + 2*k2], W3[n*HM + 2*k2+1], hi, lo);
        g_W3phi[u] = hi; g_W3plo[u] = lo;
    }
}

// ---- init: h0=0, msgsum=0, A/B for step 0 (h=0 => bias-only) ----
// mp_W1 is (64,67): [Wi(32) | Wj(32) | wJ | wbi | wbj]
__global__ __launch_bounds__(512) void init_kernel(const float* __restrict__ b,
        const float* __restrict__ W1, const float* __restrict__ b1){
    int t = blockIdx.x*512 + threadIdx.x;
    int i = t>>6, k = t&63;
    float bi = b[i];
    g_A[t] = b1[k] + bi*W1[k*67+65];
    g_B[t] = bi*W1[k*67+66];
    if (k < D) g_h[0][i*D+k] = 0.f;
    else       g_msgsum[i*M + (k-D)] = 0.f;
}

// ---------------------------------------------------------------------------
// Edge kernel (HMMA) — R12 config (measured best): block = 4 warps;
// tile = 4 i x 32 j via TWO j-passes reusing staged weights.
// ---------------------------------------------------------------------------
__global__ __launch_bounds__(128) void edge_kernel(const float* __restrict__ J,
        const float* __restrict__ W1, const float* __restrict__ b2,
        const float* __restrict__ b3){
    __shared__ u32   s_wbuf[7168];        // w2h[2304] w2l[2304] w3h[1280] w3l[1280]
    __shared__ float s_A[4][HM];
    __shared__ float s_B[32][72];
    __shared__ float s_red[4*16*33];
    __shared__ float s_wJ[HM], s_b2[HM], s_b3[M];

    u32* s_w2h = s_wbuf;
    u32* s_w2l = s_wbuf + 2304;
    u32* s_w3h = s_wbuf + 4608;
    u32* s_w3l = s_wbuf + 5888;

    const int tid  = threadIdx.x;
    const int wid  = tid>>5, lane = tid&31;
    const int g    = lane>>2, t = lane&3;
    const int j0   = blockIdx.x*32;
    const int i    = blockIdx.y*4 + wid;

    {
        const uint4* s2h = (const uint4*)g_W2phi;
        const uint4* s2l = (const uint4*)g_W2plo;
        #pragma unroll
        for (int idx = tid; idx < 512; idx += 128){
            int r = idx>>4, c4 = idx&15;
            *(uint4*)(s_w2h + r*72 + c4*4) = s2h[idx];
            *(uint4*)(s_w2l + r*72 + c4*4) = s2l[idx];
        }
        const uint4* s3h = (const uint4*)g_W3phi;
        const uint4* s3l = (const uint4*)g_W3plo;
        #pragma unroll
        for (int idx = tid; idx < 256; idx += 128){
            int r = idx>>3, c4 = idx&7;
            *(uint4*)(s_w3h + r*40 + c4*4) = s3h[idx];
            *(uint4*)(s_w3l + r*40 + c4*4) = s3l[idx];
        }
        const float4* Bg = (const float4*)(g_B + j0*HM);
        #pragma unroll
        for (int idx = tid; idx < 512; idx += 128){
            int r = idx>>4, c4 = idx&15;
            *(float4*)(&s_B[r][c4*4]) = Bg[idx];
        }
        const float4* Ag = (const float4*)(g_A + blockIdx.y*4*HM);
        #pragma unroll
        for (int idx = tid; idx < 64; idx += 128)
            *(float4*)(((float*)s_A) + idx*4) = Ag[idx];
        if (tid < HM){ s_wJ[tid] = W1[tid*67+64]; s_b2[tid] = b2[tid]; }
        if (tid < M)  s_b3[tid] = b3[tid];
    }

    float Jp[2][2];
    #pragma unroll
    for (int p = 0; p < 2; p++){
        Jp[p][0] = J[i*NN + j0 + p*16 + g];
        Jp[p][1] = J[i*NN + j0 + p*16 + g + 8];
    }
    __syncthreads();

    #pragma unroll
    for (int pass = 0; pass < 2; pass++){
        const int jb = pass*16;
        const float Jg = Jp[pass][0], Jg8 = Jp[pass][1];

        u32 ahi[4][4], alo[4][4];
        #pragma unroll
        for (int kk = 0; kk < 4; kk++){
            #pragma unroll
            for (int h = 0; h < 2; h++){
                int k = kk*16 + h*8 + t*2;
                float A0 = s_A[wid][k],  A1 = s_A[wid][k+1];
                float w0 = s_wJ[k],      w1 = s_wJ[k+1];
                float t0 = A0 + Jg *w0,  t1 = A1 + Jg *w1;
                float u0 = A0 + Jg8*w0,  u1 = A1 + Jg8*w1;
                float vg0 = fmaxf(t0 + s_B[jb+g  ][k], 0.f), vg1 = fmaxf(t1 + s_B[jb+g  ][k+1], 0.f);
                float v80 = fmaxf(u0 + s_B[jb+g+8][k], 0.f), v81 = fmaxf(u1 + s_B[jb+g+8][k+1], 0.f);
                split2(vg0, vg1, ahi[kk][2*h  ], alo[kk][2*h  ]);
                split2(v80, v81, ahi[kk][2*h+1], alo[kk][2*h+1]);
            }
        }

        float C1[8][4];
        #pragma unroll
        for (int nt = 0; nt < 8; nt++){ C1[nt][0]=C1[nt][1]=C1[nt][2]=C1[nt][3]=0.f; }
        #pragma unroll
        for (int nt = 0; nt < 8; nt++){
            #pragma unroll
            for (int kk = 0; kk < 4; kk++){
                const u32* bh = s_w2h + (kk*8+t)*72 + nt*8 + g;
                const u32* bl = s_w2l + (kk*8+t)*72 + nt*8 + g;
                u32 bh0 = bh[0], bh1 = bh[4*72];
                u32 bl0 = bl[0], bl1 = bl[4*72];
                mma16816(C1[nt], ahi[kk], bh0, bh1);
                mma16816(C1[nt], alo[kk], bh0, bh1);
                mma16816(C1[nt], ahi[kk], bl0, bl1);
            }
        }

        u32 mhi[4][4], mlo[4][4];
        #pragma unroll
        for (int kk = 0; kk < 4; kk++){
            #pragma unroll
            for (int p = 0; p < 2; p++){
                int nt = 2*kk + p;
                float bb0 = s_b2[nt*8 + t*2], bb1 = s_b2[nt*8 + t*2 + 1];
                float v0 = fmaxf(C1[nt][0]+bb0, 0.f), v1 = fmaxf(C1[nt][1]+bb1, 0.f);
                float v2 = fmaxf(C1[nt][2]+bb0, 0.f), v3 = fmaxf(C1[nt][3]+bb1, 0.f);
                split2(v0, v1, mhi[kk][2*p  ], mlo[kk][2*p  ]);
                split2(v2, v3, mhi[kk][2*p+1], mlo[kk][2*p+1]);
            }
        }

        float C2[4][4];
        #pragma unroll
        for (int nt = 0; nt < 4; nt++){ C2[nt][0]=C2[nt][1]=C2[nt][2]=C2[nt][3]=0.f; }
        #pragma unroll
        for (int nt = 0; nt < 4; nt++){
            #pragma unroll
            for (int kk = 0; kk < 4; kk++){
                const u32* bh = s_w3h + (kk*8+t)*40 + nt*8 + g;
                const u32* bl = s_w3l + (kk*8+t)*40 + nt*8 + g;
                u32 bh0 = bh[0], bh1 = bh[4*40];
                u32 bl0 = bl[0], bl1 = bl[4*40];
                mma16816(C2[nt], mhi[kk], bh0, bh1);
                mma16816(C2[nt], mlo[kk], bh0, bh1);
                mma16816(C2[nt], mhi[kk], bl0, bl1);
            }
        }

        #pragma unroll
        for (int nt = 0; nt < 4; nt++){
            int c = nt*8 + t*2;
            float bb0 = s_b3[c], bb1 = s_b3[c+1];
            s_red[wid*528 + g*33     + c    ] = fmaxf(C2[nt][0]+bb0, 0.f);
            s_red[wid*528 + g*33     + c + 1] = fmaxf(C2[nt][1]+bb1, 0.f);
            s_red[wid*528 + (g+8)*33 + c    ] = fmaxf(C2[nt][2]+bb0, 0.f);
            s_red[wid*528 + (g+8)*33 + c + 1] = fmaxf(C2[nt][3]+bb1, 0.f);
        }
        __syncthreads();
        #pragma unroll
        for (int v = tid; v < 512; v += 128){
            int r = v>>5, c = v&31;
            float s = s_red[r*33+c] + s_red[528+r*33+c] + s_red[1056+r*33+c] + s_red[1584+r*33+c];
            atomicAdd(&g_msgsum[(j0+jb+r)*M + c], s);
        }
        __syncthreads();
    }
}

// ---------------------------------------------------------------------------
// Update: 2 nodes per block, 320 threads, NO register weight preload (avoids
// the regs=128 spill of R13). Gate threads (0..191) read Wih/Whh via __ldg in
// the FMA loop (L1-resident after warmup, MLP=16). W1 staged COALESCED into
// smem (stride 69 => conflict-free prep reads) overlapping the gate phase.
// ---------------------------------------------------------------------------
__global__ __launch_bounds__(320) void update_kernel(
        const float* __restrict__ Wih, const float* __restrict__ Whh,
        const float* __restrict__ bih, const float* __restrict__ bhh,
        const float* __restrict__ b,   const float* __restrict__ W1,
        const float* __restrict__ b1,  int cur, int nxt){
    __shared__ float W1s[64*69];              // padded stride 69: prep conflict-free
    __shared__ float xs[2][D+M];
    __shared__ float gi[2][3*D], gh[2][3*D], hn[2][D];
    const int tid = threadIdx.x, n0 = blockIdx.x*2;

    // coalesced W1 staging (all 320 threads; overlaps gate-weight misses)
    for (int idx = tid; idx < 64*67; idx += 320)
        W1s[(idx/67)*69 + (idx%67)] = W1[idx];
    if (tid < 2*(D+M)){
        int nd = tid>>6, c = tid&63;
        xs[nd][c] = (c < D) ? g_h[cur][(n0+nd)*D+c] : g_msgsum[(n0+nd)*M+(c-D)];
    }
    __syncthreads();

    if (tid < 192){                            // gate rows: nd = tid/96, r = tid%96
        const int nd = tid/96, r = tid%96;
        const float4* Wr = (const float4*)(Wih + r*(D+M));
        const float4* Hr = (const float4*)(Whh + r*D);
        const float4* xv = (const float4*)xs[nd];
        float a0 = __ldg(bih+r), a1 = 0.f, a2 = 0.f, a3 = 0.f;
        #pragma unroll
        for (int q = 0; q < 16; q++){
            float4 w = __ldg(Wr+q); float4 x = xv[q];
            a0 = fmaf(w.x, x.x, a0); a1 = fmaf(w.y, x.y, a1);
            a2 = fmaf(w.z, x.z, a2); a3 = fmaf(w.w, x.w, a3);
        }
        gi[nd][r] = (a0+a1)+(a2+a3);
        float h0 = __ldg(bhh+r), h1 = 0.f, h2 = 0.f, h3 = 0.f;
        #pragma unroll
        for (int q = 0; q < 8; q++){
            float4 w = __ldg(Hr+q); float4 x = xv[q];
            h0 = fmaf(w.x, x.x, h0); h1 = fmaf(w.y, x.y, h1);
            h2 = fmaf(w.z, x.z, h2); h3 = fmaf(w.w, x.w, h3);
        }
        gh[nd][r] = (h0+h1)+(h2+h3);
    }
    __syncthreads();

    if (tid < 2*D){
        int nd = tid>>5, tt = tid&31;
        float rr = sigmoidf(gi[nd][tt]     + gh[nd][tt]);
        float zz = sigmoidf(gi[nd][D+tt]   + gh[nd][D+tt]);
        float ng = tanhf   (gi[nd][2*D+tt] + rr*gh[nd][2*D+tt]);
        float hv = (1.f-zz)*ng + zz*xs[nd][tt];
        hn[nd][tt] = hv;
        g_h[nxt][(n0+nd)*D+tt] = hv;
        g_msgsum[(n0+nd)*M+tt] = 0.f;          // re-zero for next step
    }
    __syncthreads();

    if (tid >= 192){                           // prep: 128 threads = 2 nodes x 64 k
        const int u = tid - 192, nd = u>>6, k = u&63, i = n0+nd;
        const float* row = W1s + k*69;         // smem, stride 69: conflict-free
        const float bi = __ldg(b + i);
        float a  = __ldg(b1 + k) + bi*row[65];
        float bb = bi*row[66];
        float ax = 0.f, bx = 0.f;
        #pragma unroll
        for (int d0 = 0; d0 < D; d0 += 2){
            float h0 = hn[nd][d0], h1 = hn[nd][d0+1];
            a  = fmaf(h0, row[d0],    a);   ax = fmaf(h1, row[d0+1],   ax);
            bb = fmaf(h0, row[D+d0], bb);   bx = fmaf(h1, row[D+d0+1], bx);
        }
        g_A[i*HM+k] = a + ax;
        g_B[i*HM+k] = bb + bx;
    }
}

// ---- readout ----
__global__ void readout_kernel(const float* __restrict__ rW1,const float* __restrict__ rb1,
        const float* __restrict__ rW2,const float* __restrict__ rb2,
        const float* __restrict__ rW3,const float* __restrict__ rb3,
        int cur, float* __restrict__ out){
    __shared__ float hs[D], y1[HM], y2[HM];
    const int n = blockIdx.x, t = threadIdx.x;
    if (t < D) hs[t] = g_h[cur][n*D+t];
    __syncthreads();
    float a = rb1[t];
    #pragma unroll
    for (int c = 0; c < D; c++) a = fmaf(rW1[t*D+c], hs[c], a);
    y1[t] = fmaxf(a, 0.f);
    __syncthreads();
    a = rb2[t];
    #pragma unroll
    for (int c = 0; c < HM; c++) a = fmaf(rW2[t*HM+c], y1[c], a);
    y2[t] = fmaxf(a, 0.f);
    __syncthreads();
    if (t < 2){
        a = rb3[t];
        #pragma unroll
        for (int c = 0; c < HM; c++) a = fmaf(rW3[t*HM+c], y2[c], a);
        out[n*2+t] = 1.f/(1.f+expf(-fmaxf(a, 0.f)));
    }
}

extern "C" void kernel_launch(void* const* d_in, const int* in_sizes, int n_in,
                              void* d_out, int out_size){
    const float* J  =(const float*)d_in[0];
    const float* b  =(const float*)d_in[1];
    const float* W1 =(const float*)d_in[2];
    const float* b1 =(const float*)d_in[3];
    const float* W2 =(const float*)d_in[4];
    const float* b2 =(const float*)d_in[5];
    const float* W3 =(const float*)d_in[6];
    const float* b3 =(const float*)d_in[7];
    const float* Wih=(const float*)d_in[8];
    const float* Whh=(const float*)d_in[9];
    const float* bih=(const float*)d_in[10];
    const float* bhh=(const float*)d_in[11];
    const float* rW1=(const float*)d_in[12];
    const float* rb1=(const float*)d_in[13];
    const float* rW2=(const float*)d_in[14];
    const float* rb2=(const float*)d_in[15];
    const float* rW3=(const float*)d_in[16];
    const float* rb3=(const float*)d_in[17];
    float* out = (float*)d_out;

    init_kernel<<<64,512>>>(b, W1, b1);
    split_kernel<<<6,512>>>(W2, W3);

    int cur = 0;
    for (int s = 0; s < NSTEPS; s++){
        edge_kernel<<<dim3(NN/32, NN/4),128>>>(J, W1, b2, b3);
        update_kernel<<<NN/2,320>>>(Wih, Whh, bih, bhh, b, W1, b1, cur, 1-cur);
        cur = 1-cur;
    }
    readout_kernel<<<NN,HM>>>(rW1, rb1, rW2, rb2, rW3, rb3, cur, out);
}

// round 17
// speedup vs baseline: 1.2881x; 1.2343x over previous
#include <cuda_runtime.h>
#include <cuda_bf16.h>
#include <math.h>
#include <cstdint>

#define NN 512
#define D  32
#define M  32
#define HM 64
#define NSTEPS 5

typedef unsigned int u32;

// ---- scratch (device globals; no allocation allowed) ----
__device__ float g_h[2][NN*D];
__device__ float g_A[NN*HM];
__device__ float g_B[NN*HM];
__device__ float g_msgsum[NN*M];
__device__ u32 g_W2phi[32*64];          // bf16x2 hi plane: B[k][n] = W2[n][k]
__device__ u32 g_W3phi[32*32];          // bf16x2 hi plane: B[k][n] = W3[n][k]

__device__ __forceinline__ float sigmoidf(float x){ return 1.f/(1.f+expf(-x)); }

__device__ __forceinline__ void split2(float v0, float v1, u32& hi, u32& lo){
    __nv_bfloat162 h = __float22bfloat162_rn(make_float2(v0, v1));
    float r0 = v0 - __low2float(h), r1 = v1 - __high2float(h);
    __nv_bfloat162 l = __float22bfloat162_rn(make_float2(r0, r1));
    hi = *(u32*)&h; lo = *(u32*)&l;
}

// warp-level bf16 MMA, f32 accum (baseline PTX, sm_80+)
__device__ __forceinline__ void mma16816(float* c, const u32* a, u32 b0, u32 b1){
    asm volatile("mma.sync.aligned.m16n8k16.row.col.f32.bf16.bf16.f32 "
        "{%0,%1,%2,%3}, {%4,%5,%6,%7}, {%8,%9}, {%0,%1,%2,%3};"
        : "+f"(c[0]),"+f"(c[1]),"+f"(c[2]),"+f"(c[3])
        : "r"(a[0]),"r"(a[1]),"r"(a[2]),"r"(a[3]), "r"(b0),"r"(b1));
}

// ---- pack weights into bf16x2 hi planes (constant per replay) ----
// 2-term emulation: activations are split hi/lo, weights only hi (bf16-rounded).
__global__ void split_kernel(const float* __restrict__ W2, const float* __restrict__ W3){
    int t = blockIdx.x*512 + threadIdx.x;
    if (t < 32*64){                       // B[k][n] = W2[n][k]
        int k2 = t>>6, n = t&63;
        u32 hi, lo; split2(W2[n*HM + 2*k2], W2[n*HM + 2*k2+1], hi, lo);
        g_W2phi[t] = hi;
    } else if (t < 32*64 + 32*32){        // B[k][n] = W3[n][k]
        int u = t - 32*64;
        int k2 = u>>5, n = u&31;
        u32 hi, lo; split2(W3[n*HM + 2*k2], W3[n*HM + 2*k2+1], hi, lo);
        g_W3phi[u] = hi;
    }
}

// ---- init: h0=0, msgsum=0, A/B for step 0 (h=0 => bias-only) ----
// mp_W1 is (64,67): [Wi(32) | Wj(32) | wJ | wbi | wbj]
__global__ __launch_bounds__(512) void init_kernel(const float* __restrict__ b,
        const float* __restrict__ W1, const float* __restrict__ b1){
    int t = blockIdx.x*512 + threadIdx.x;
    int i = t>>6, k = t&63;
    float bi = b[i];
    g_A[t] = b1[k] + bi*W1[k*67+65];
    g_B[t] = bi*W1[k*67+66];
    if (k < D) g_h[0][i*D+k] = 0.f;
    else       g_msgsum[i*M + (k-D)] = 0.f;
}

// ---------------------------------------------------------------------------
// Edge kernel (HMMA, 2-term): block = 4 warps; tile = 4 i x 32 j via TWO
// j-passes reusing staged weights. Warp per pass: 1 i x 16 j.
//   m1 = relu(A[i]+B[j]+J*wJ) -> hi/lo frags (regs)
//   C1 = (m1hi+m1lo) @ W2hi^T  -> m2 = relu(C1+b2) re-split (regs only)
//   C2 = (m2hi+m2lo) @ W3hi^T  -> msg = relu(C2+b3), 4-warp reduce, atomics
// ---------------------------------------------------------------------------
__global__ __launch_bounds__(128) void edge_kernel(const float* __restrict__ J,
        const float* __restrict__ W1, const float* __restrict__ b2,
        const float* __restrict__ b3){
    __shared__ u32   s_wbuf[3584];        // w2h[2304] w3h[1280]  (hi planes only)
    __shared__ float s_A[4][HM];
    __shared__ float s_B[32][72];
    __shared__ float s_red[4*16*33];
    __shared__ float s_wJ[HM], s_b2[HM], s_b3[M];

    u32* s_w2h = s_wbuf;
    u32* s_w3h = s_wbuf + 2304;

    const int tid  = threadIdx.x;
    const int wid  = tid>>5, lane = tid&31;
    const int g    = lane>>2, t = lane&3;
    const int j0   = blockIdx.x*32;
    const int i    = blockIdx.y*4 + wid;

    {
        const uint4* s2h = (const uint4*)g_W2phi;
        #pragma unroll
        for (int idx = tid; idx < 512; idx += 128){
            int r = idx>>4, c4 = idx&15;
            *(uint4*)(s_w2h + r*72 + c4*4) = s2h[idx];
        }
        const uint4* s3h = (const uint4*)g_W3phi;
        #pragma unroll
        for (int idx = tid; idx < 256; idx += 128){
            int r = idx>>3, c4 = idx&7;
            *(uint4*)(s_w3h + r*40 + c4*4) = s3h[idx];
        }
        const float4* Bg = (const float4*)(g_B + j0*HM);
        #pragma unroll
        for (int idx = tid; idx < 512; idx += 128){
            int r = idx>>4, c4 = idx&15;
            *(float4*)(&s_B[r][c4*4]) = Bg[idx];
        }
        const float4* Ag = (const float4*)(g_A + blockIdx.y*4*HM);
        #pragma unroll
        for (int idx = tid; idx < 64; idx += 128)
            *(float4*)(((float*)s_A) + idx*4) = Ag[idx];
        if (tid < HM){ s_wJ[tid] = W1[tid*67+64]; s_b2[tid] = b2[tid]; }
        if (tid < M)  s_b3[tid] = b3[tid];
    }

    float Jp[2][2];
    #pragma unroll
    for (int p = 0; p < 2; p++){
        Jp[p][0] = J[i*NN + j0 + p*16 + g];
        Jp[p][1] = J[i*NN + j0 + p*16 + g + 8];
    }
    __syncthreads();

    #pragma unroll
    for (int pass = 0; pass < 2; pass++){
        const int jb = pass*16;
        const float Jg = Jp[pass][0], Jg8 = Jp[pass][1];

        // ---- m1 A-fragments (4 k-steps x 4 regs, hi/lo) ----
        u32 ahi[4][4], alo[4][4];
        #pragma unroll
        for (int kk = 0; kk < 4; kk++){
            #pragma unroll
            for (int h = 0; h < 2; h++){
                int k = kk*16 + h*8 + t*2;
                float A0 = s_A[wid][k],  A1 = s_A[wid][k+1];
                float w0 = s_wJ[k],      w1 = s_wJ[k+1];
                float t0 = A0 + Jg *w0,  t1 = A1 + Jg *w1;
                float u0 = A0 + Jg8*w0,  u1 = A1 + Jg8*w1;
                float vg0 = fmaxf(t0 + s_B[jb+g  ][k], 0.f), vg1 = fmaxf(t1 + s_B[jb+g  ][k+1], 0.f);
                float v80 = fmaxf(u0 + s_B[jb+g+8][k], 0.f), v81 = fmaxf(u1 + s_B[jb+g+8][k+1], 0.f);
                split2(vg0, vg1, ahi[kk][2*h  ], alo[kk][2*h  ]);
                split2(v80, v81, ahi[kk][2*h+1], alo[kk][2*h+1]);
            }
        }

        // ---- GEMM1: C1[16x64] = (m1hi+m1lo) @ W2hi^T (2-term) ----
        float C1[8][4];
        #pragma unroll
        for (int nt = 0; nt < 8; nt++){ C1[nt][0]=C1[nt][1]=C1[nt][2]=C1[nt][3]=0.f; }
        #pragma unroll
        for (int nt = 0; nt < 8; nt++){
            #pragma unroll
            for (int kk = 0; kk < 4; kk++){
                const u32* bh = s_w2h + (kk*8+t)*72 + nt*8 + g;
                u32 bh0 = bh[0], bh1 = bh[4*72];
                mma16816(C1[nt], ahi[kk], bh0, bh1);
                mma16816(C1[nt], alo[kk], bh0, bh1);
            }
        }

        // ---- m2 = relu(C1+b2): C-frag layout == A-frag layout (regs only) ----
        u32 mhi[4][4], mlo[4][4];
        #pragma unroll
        for (int kk = 0; kk < 4; kk++){
            #pragma unroll
            for (int p = 0; p < 2; p++){
                int nt = 2*kk + p;
                float bb0 = s_b2[nt*8 + t*2], bb1 = s_b2[nt*8 + t*2 + 1];
                float v0 = fmaxf(C1[nt][0]+bb0, 0.f), v1 = fmaxf(C1[nt][1]+bb1, 0.f);
                float v2 = fmaxf(C1[nt][2]+bb0, 0.f), v3 = fmaxf(C1[nt][3]+bb1, 0.f);
                split2(v0, v1, mhi[kk][2*p  ], mlo[kk][2*p  ]);
                split2(v2, v3, mhi[kk][2*p+1], mlo[kk][2*p+1]);
            }
        }

        // ---- GEMM2: C2[16x32] = (m2hi+m2lo) @ W3hi^T (2-term) ----
        float C2[4][4];
        #pragma unroll
        for (int nt = 0; nt < 4; nt++){ C2[nt][0]=C2[nt][1]=C2[nt][2]=C2[nt][3]=0.f; }
        #pragma unroll
        for (int nt = 0; nt < 4; nt++){
            #pragma unroll
            for (int kk = 0; kk < 4; kk++){
                const u32* bh = s_w3h + (kk*8+t)*40 + nt*8 + g;
                u32 bh0 = bh[0], bh1 = bh[4*40];
                mma16816(C2[nt], mhi[kk], bh0, bh1);
                mma16816(C2[nt], mlo[kk], bh0, bh1);
            }
        }

        // ---- msg = relu(C2+b3); reduce over 4 warps (i's); atomics per j ----
        #pragma unroll
        for (int nt = 0; nt < 4; nt++){
            int c = nt*8 + t*2;
            float bb0 = s_b3[c], bb1 = s_b3[c+1];
            s_red[wid*528 + g*33     + c    ] = fmaxf(C2[nt][0]+bb0, 0.f);
            s_red[wid*528 + g*33     + c + 1] = fmaxf(C2[nt][1]+bb1, 0.f);
            s_red[wid*528 + (g+8)*33 + c    ] = fmaxf(C2[nt][2]+bb0, 0.f);
            s_red[wid*528 + (g+8)*33 + c + 1] = fmaxf(C2[nt][3]+bb1, 0.f);
        }
        __syncthreads();
        #pragma unroll
        for (int v = tid; v < 512; v += 128){
            int r = v>>5, c = v&31;
            float s = s_red[r*33+c] + s_red[528+r*33+c] + s_red[1056+r*33+c] + s_red[1584+r*33+c];
            atomicAdd(&g_msgsum[(j0+jb+r)*M + c], s);
        }
        __syncthreads();
    }
}

// ---------------------------------------------------------------------------
// Update — R11 measured-best structure (12.9us) + bank-conflict padding ONLY.
// 4 nodes/block, 384 threads, gate weights staged in padded smem; A/B prep via
// direct __ldg (no serial W1 smem staging phase — that was R12's regression).
// ---------------------------------------------------------------------------
__global__ __launch_bounds__(384) void update_kernel(
        const float* __restrict__ Wih, const float* __restrict__ Whh,
        const float* __restrict__ bih, const float* __restrict__ bhh,
        const float* __restrict__ b,   const float* __restrict__ W1,
        const float* __restrict__ b1,  int cur, int nxt){
    __shared__ float Wihs[3*D][D+M+1];   // stride 65: conflict-free row-per-lane
    __shared__ float Whhs[3*D][D+1];     // stride 33
    __shared__ float bihs[3*D], bhhs[3*D];
    __shared__ float xs[4][D+M], gis[4][3*D], ghs[4][3*D], hn[4][D];
    const int tid = threadIdx.x, n0 = blockIdx.x*4;

    for (int idx = tid; idx < 3*D*(D+M); idx += 384) Wihs[idx>>6][idx&63] = Wih[idx];
    for (int idx = tid; idx < 3*D*D;     idx += 384) Whhs[idx>>5][idx&31] = Whh[idx];
    if (tid < 3*D){ bihs[tid] = bih[tid]; bhhs[tid] = bhh[tid]; }
    if (tid < 4*(D+M)){ int nd = tid>>6, c = tid&63;
        xs[nd][c] = (c < D) ? g_h[cur][(n0+nd)*D+c] : g_msgsum[(n0+nd)*M+(c-D)];
    }
    __syncthreads();

    const int ln = tid/(3*D), r = tid%(3*D);
    float a0=0,a1=0,a2=0,a3=0;
    #pragma unroll
    for (int c = 0; c < D+M; c += 4){
        a0=fmaf(Wihs[r][c],xs[ln][c],a0);     a1=fmaf(Wihs[r][c+1],xs[ln][c+1],a1);
        a2=fmaf(Wihs[r][c+2],xs[ln][c+2],a2); a3=fmaf(Wihs[r][c+3],xs[ln][c+3],a3);
    }
    gis[ln][r]=(a0+a1)+(a2+a3)+bihs[r];
    float h0=0,h1=0,h2=0,h3=0;
    #pragma unroll
    for (int c = 0; c < D; c += 4){
        h0=fmaf(Whhs[r][c],xs[ln][c],h0);     h1=fmaf(Whhs[r][c+1],xs[ln][c+1],h1);
        h2=fmaf(Whhs[r][c+2],xs[ln][c+2],h2); h3=fmaf(Whhs[r][c+3],xs[ln][c+3],h3);
    }
    ghs[ln][r]=(h0+h1)+(h2+h3)+bhhs[r];
    __syncthreads();

    if (tid < 4*D){
        int nd = tid>>5, tt = tid&31;
        float rr = sigmoidf(gis[nd][tt]      + ghs[nd][tt]);
        float zz = sigmoidf(gis[nd][D+tt]    + ghs[nd][D+tt]);
        float ng = tanhf   (gis[nd][2*D+tt]  + rr*ghs[nd][2*D+tt]);
        float hv = (1.f-zz)*ng + zz*xs[nd][tt];
        hn[nd][tt] = hv;
        g_h[nxt][(n0+nd)*D+tt] = hv;
        g_msgsum[(n0+nd)*M+tt] = 0.f;        // re-zero for next step
    }
    __syncthreads();

    if (tid < 256){                           // next-step A/B from h_new (__ldg, as R11)
        int nd = tid>>6, k = tid&63, i = n0+nd;
        float bi = b[i];
        const float* row = W1 + k*67;
        float a = b1[k] + bi*__ldg(row+65), bb = bi*__ldg(row+66);
        float ax = 0.f, bx = 0.f;
        #pragma unroll
        for (int d0 = 0; d0 < D; d0 += 2){
            float hv0 = hn[nd][d0], hv1 = hn[nd][d0+1];
            a  = fmaf(hv0, __ldg(row+d0),     a);   ax = fmaf(hv1, __ldg(row+d0+1),   ax);
            bb = fmaf(hv0, __ldg(row+D+d0),  bb);   bx = fmaf(hv1, __ldg(row+D+d0+1), bx);
        }
        g_A[i*HM+k] = a + ax;
        g_B[i*HM+k] = bb + bx;
    }
}

// ---- readout ----
__global__ void readout_kernel(const float* __restrict__ rW1,const float* __restrict__ rb1,
        const float* __restrict__ rW2,const float* __restrict__ rb2,
        const float* __restrict__ rW3,const float* __restrict__ rb3,
        int cur, float* __restrict__ out){
    __shared__ float hs[D], y1[HM], y2[HM];
    const int n = blockIdx.x, t = threadIdx.x;
    if (t < D) hs[t] = g_h[cur][n*D+t];
    __syncthreads();
    float a = rb1[t];
    #pragma unroll
    for (int c = 0; c < D; c++) a = fmaf(rW1[t*D+c], hs[c], a);
    y1[t] = fmaxf(a, 0.f);
    __syncthreads();
    a = rb2[t];
    #pragma unroll
    for (int c = 0; c < HM; c++) a = fmaf(rW2[t*HM+c], y1[c], a);
    y2[t] = fmaxf(a, 0.f);
    __syncthreads();
    if (t < 2){
        a = rb3[t];
        #pragma unroll
        for (int c = 0; c < HM; c++) a = fmaf(rW3[t*HM+c], y2[c], a);
        out[n*2+t] = 1.f/(1.f+expf(-fmaxf(a, 0.f)));
    }
}

extern "C" void kernel_launch(void* const* d_in, const int* in_sizes, int n_in,
                              void* d_out, int out_size){
    const float* J  =(const float*)d_in[0];
    const float* b  =(const float*)d_in[1];
    const float* W1 =(const float*)d_in[2];
    const float* b1 =(const float*)d_in[3];
    const float* W2 =(const float*)d_in[4];
    const float* b2 =(const float*)d_in[5];
    const float* W3 =(const float*)d_in[6];
    const float* b3 =(const float*)d_in[7];
    const float* Wih=(const float*)d_in[8];
    const float* Whh=(const float*)d_in[9];
    const float* bih=(const float*)d_in[10];
    const float* bhh=(const float*)d_in[11];
    const float* rW1=(const float*)d_in[12];
    const float* rb1=(const float*)d_in[13];
    const float* rW2=(const float*)d_in[14];
    const float* rb2=(const float*)d_in[15];
    const float* rW3=(const float*)d_in[16];
    const float* rb3=(const float*)d_in[17];
    float* out = (float*)d_out;

    init_kernel<<<64,512>>>(b, W1, b1);
    split_kernel<<<6,512>>>(W2, W3);

    int cur = 0;
    for (int s = 0; s < NSTEPS; s++){
        edge_kernel<<<dim3(NN/32, NN/4),128>>>(J, W1, b2, b3);
        update_kernel<<<NN/4,384>>>(Wih, Whh, bih, bhh, b, W1, b1, cur, 1-cur);
        cur = 1-cur;
    }
    readout_kernel<<<NN,HM>>>(rW1, rb1, rW2, rb2, rW3, rb3, cur, out);
}